// round 2
// baseline (speedup 1.0000x reference)
#include <cuda_runtime.h>
#include <cuda_bf16.h>
#include <cstddef>

// ---------------------------------------------------------------------------
// EncoderLayer: B=4, S=2048, D=768, H=12, Dh=64, FFN=3072, fp32
// Pipeline: QKV gemms -> flash attention -> add+LN -> FFN gemm x2 -> add+LN
// Mask is read as 32-bit words (bool widened to int32/float32 by harness);
// nonzero word == masked.
// ---------------------------------------------------------------------------

#define B_SZ   4
#define S_LEN  2048
#define D_HID  768
#define NH     12
#define DH     64
#define D_FFN  3072
#define M_ROWS (B_SZ * S_LEN)   // 8192

// ---------------- scratch (static device allocations, allowed) -------------
__device__ float g_q[M_ROWS * D_HID];
__device__ float g_k[M_ROWS * D_HID];
__device__ float g_v[M_ROWS * D_HID];
__device__ float g_attn[M_ROWS * D_HID];
__device__ float g_ln1[M_ROWS * D_HID];
__device__ float g_hid[(size_t)M_ROWS * D_FFN];
__device__ float g_ffn[M_ROWS * D_HID];

// ---------------------------------------------------------------------------
// SGEMM: C[M,N] = A[M,K] @ W[K,N] + bias
// 128x128x16 tile, 256 threads, 8x8 microtile.
// EPI==0: C[m*N+n] ; EPI==1: scatter to [B,H,S,Dh] layout (QKV projections)
// ---------------------------------------------------------------------------
template <int EPI>
__global__ void __launch_bounds__(256) sgemm_kernel(
    const float* __restrict__ A, const float* __restrict__ W,
    const float* __restrict__ bias, float* __restrict__ C,
    int M, int N, int K)
{
    __shared__ __align__(16) float As[16][136];  // [k][m], padded for f4 + banks
    __shared__ __align__(16) float Bs[16][128];  // [k][n]

    const int bm = blockIdx.y * 128;
    const int bn = blockIdx.x * 128;
    const int tid = threadIdx.x;
    const int tx = tid & 15;        // 0..15 -> n
    const int ty = tid >> 4;        // 0..15 -> m

    float acc[8][8];
#pragma unroll
    for (int i = 0; i < 8; i++)
#pragma unroll
        for (int j = 0; j < 8; j++) acc[i][j] = 0.f;

    for (int k0 = 0; k0 < K; k0 += 16) {
        // load A tile (128 rows x 16 k)
#pragma unroll
        for (int i = 0; i < 8; i++) {
            int idx = i * 256 + tid;
            int r = idx >> 4, c = idx & 15;
            As[c][r] = A[(size_t)(bm + r) * K + k0 + c];
        }
        // load B tile (16 k x 128 n)
#pragma unroll
        for (int i = 0; i < 8; i++) {
            int idx = i * 256 + tid;
            int r = idx >> 7, c = idx & 127;
            Bs[r][c] = W[(size_t)(k0 + r) * N + bn + c];
        }
        __syncthreads();

#pragma unroll
        for (int kk = 0; kk < 16; kk++) {
            float a[8], b[8];
            *(float4*)&a[0] = *(const float4*)&As[kk][ty * 8];
            *(float4*)&a[4] = *(const float4*)&As[kk][ty * 8 + 4];
            *(float4*)&b[0] = *(const float4*)&Bs[kk][tx * 8];
            *(float4*)&b[4] = *(const float4*)&Bs[kk][tx * 8 + 4];
#pragma unroll
            for (int i = 0; i < 8; i++)
#pragma unroll
                for (int j = 0; j < 8; j++)
                    acc[i][j] += a[i] * b[j];
        }
        __syncthreads();
    }

#pragma unroll
    for (int i = 0; i < 8; i++) {
        int m = bm + ty * 8 + i;
#pragma unroll
        for (int j = 0; j < 8; j++) {
            int n = bn + tx * 8 + j;
            float val = acc[i][j] + bias[n];
            if (EPI == 0) {
                C[(size_t)m * N + n] = val;
            } else {
                // m = b*S + s ; n = h*64 + dh -> [((b*H+h)*S + s)*64 + dh]
                int b = m >> 11, s = m & 2047;
                int h = n >> 6, dh = n & 63;
                C[((size_t)(b * NH + h) * S_LEN + s) * DH + dh] = val;
            }
        }
    }
}

// ---------------------------------------------------------------------------
// Flash attention, fp32. Per block: one (b,h) and a 64-query tile.
// 256 threads; thread (tq, tk) owns 4 query rows x 4 key cols (scores) and
// 4 query rows x 4 head-dims (output).
// Q pre-scaled by 1/8. Masked scores set to exactly -1e9 (matches reference).
// Mask elements are 32-bit words; nonzero == masked.
// ---------------------------------------------------------------------------
#define FLASH_SMEM (4 * 64 * 65 * 4)

__global__ void __launch_bounds__(256) flash_kernel(
    const float* __restrict__ Q, const float* __restrict__ K,
    const float* __restrict__ V, const unsigned int* __restrict__ mask,
    float* __restrict__ out)
{
    extern __shared__ float sm[];
    float (*Qs)[65] = (float(*)[65])(sm);
    float (*Ks)[65] = (float(*)[65])(sm + 64 * 65);
    float (*Vs)[65] = (float(*)[65])(sm + 2 * 64 * 65);
    float (*Ps)[65] = (float(*)[65])(sm + 3 * 64 * 65);

    const int q0 = blockIdx.x * 64;
    const int h = blockIdx.y;
    const int b = blockIdx.z;
    const int tid = threadIdx.x;
    const int tq = tid >> 4;   // 0..15
    const int tk = tid & 15;   // 0..15

    const float* Qg = Q + ((size_t)(b * NH + h) * S_LEN + q0) * DH;
    const float* Kg = K + (size_t)(b * NH + h) * S_LEN * DH;
    const float* Vg = V + (size_t)(b * NH + h) * S_LEN * DH;
    const unsigned int* Mg = mask + ((size_t)b * S_LEN + q0) * S_LEN;

    // load Q tile (scaled by 1/sqrt(Dh))
#pragma unroll
    for (int i = 0; i < 16; i++) {
        int idx = i * 256 + tid;
        int r = idx >> 6, d = idx & 63;
        Qs[r][d] = Qg[idx] * 0.125f;
    }

    float m_i[4], l_i[4], o[4][4];
#pragma unroll
    for (int i = 0; i < 4; i++) {
        m_i[i] = -1e30f;
        l_i[i] = 0.f;
#pragma unroll
        for (int j = 0; j < 4; j++) o[i][j] = 0.f;
    }

    for (int kt = 0; kt < S_LEN / 64; kt++) {
        __syncthreads();   // prior PV done (and Qs visible on first iter)
        // load K,V tiles (64 keys x 64 dims each)
#pragma unroll
        for (int i = 0; i < 16; i++) {
            int idx = i * 256 + tid;
            int r = idx >> 6, d = idx & 63;
            Ks[r][d] = Kg[(size_t)kt * 4096 + idx];
            Vs[r][d] = Vg[(size_t)kt * 4096 + idx];
        }
        __syncthreads();

        // scores 4x4
        float s[4][4];
#pragma unroll
        for (int i = 0; i < 4; i++)
#pragma unroll
            for (int j = 0; j < 4; j++) s[i][j] = 0.f;

#pragma unroll 8
        for (int d = 0; d < 64; d++) {
            float qr[4], kr[4];
#pragma unroll
            for (int i = 0; i < 4; i++) qr[i] = Qs[tq * 4 + i][d];
#pragma unroll
            for (int j = 0; j < 4; j++) kr[j] = Ks[tk * 4 + j][d];
#pragma unroll
            for (int i = 0; i < 4; i++)
#pragma unroll
                for (int j = 0; j < 4; j++) s[i][j] += qr[i] * kr[j];
        }

        // mask (32-bit words; nonzero == masked)
#pragma unroll
        for (int i = 0; i < 4; i++) {
            uint4 mm = *(const uint4*)(Mg + (size_t)(tq * 4 + i) * S_LEN +
                                       kt * 64 + tk * 4);
            if (mm.x) s[i][0] = -1e9f;
            if (mm.y) s[i][1] = -1e9f;
            if (mm.z) s[i][2] = -1e9f;
            if (mm.w) s[i][3] = -1e9f;
        }

        // online softmax per query row (row shared by 16 threads: same tq)
#pragma unroll
        for (int i = 0; i < 4; i++) {
            float mt = fmaxf(fmaxf(s[i][0], s[i][1]), fmaxf(s[i][2], s[i][3]));
#pragma unroll
            for (int off = 8; off > 0; off >>= 1)
                mt = fmaxf(mt, __shfl_xor_sync(0xffffffffu, mt, off));
            float mn = fmaxf(m_i[i], mt);
            float alpha = __expf(m_i[i] - mn);
            float ls = 0.f;
#pragma unroll
            for (int j = 0; j < 4; j++) {
                float p = __expf(s[i][j] - mn);
                s[i][j] = p;
                ls += p;
            }
#pragma unroll
            for (int off = 8; off > 0; off >>= 1)
                ls += __shfl_xor_sync(0xffffffffu, ls, off);
            l_i[i] = l_i[i] * alpha + ls;
            m_i[i] = mn;
#pragma unroll
            for (int j = 0; j < 4; j++) o[i][j] *= alpha;
            Ps[tq * 4 + i][tk * 4 + 0] = s[i][0];
            Ps[tq * 4 + i][tk * 4 + 1] = s[i][1];
            Ps[tq * 4 + i][tk * 4 + 2] = s[i][2];
            Ps[tq * 4 + i][tk * 4 + 3] = s[i][3];
        }
        __syncthreads();

        // O += P @ V  (thread owns rows tq*4.., dims tk*4..)
#pragma unroll 8
        for (int j = 0; j < 64; j++) {
            float vr[4], pr[4];
#pragma unroll
            for (int jj = 0; jj < 4; jj++) vr[jj] = Vs[j][tk * 4 + jj];
#pragma unroll
            for (int i = 0; i < 4; i++) pr[i] = Ps[tq * 4 + i][j];
#pragma unroll
            for (int i = 0; i < 4; i++)
#pragma unroll
                for (int jj = 0; jj < 4; jj++) o[i][jj] += pr[i] * vr[jj];
        }
    }

    // write out in [B,S,D] with head offset
#pragma unroll
    for (int i = 0; i < 4; i++) {
        float inv = 1.f / l_i[i];
        size_t base = ((size_t)(b * S_LEN + q0 + tq * 4 + i)) * D_HID + h * DH + tk * 4;
#pragma unroll
        for (int j = 0; j < 4; j++)
            out[base + j] = o[i][j] * inv;
    }
}

// ---------------------------------------------------------------------------
// out = LayerNorm(A + B) * g + beta      one block per row of 768
// ---------------------------------------------------------------------------
__global__ void __launch_bounds__(256) add_ln_kernel(
    const float* __restrict__ A, const float* __restrict__ Bv,
    const float* __restrict__ g, const float* __restrict__ be,
    float* __restrict__ out)
{
    const int row = blockIdx.x;
    const float* a = A + (size_t)row * D_HID;
    const float* b = Bv + (size_t)row * D_HID;
    float* o = out + (size_t)row * D_HID;
    const int tid = threadIdx.x;

    float x[3];
    float s = 0.f, s2 = 0.f;
#pragma unroll
    for (int i = 0; i < 3; i++) {
        int c = tid + i * 256;
        float v = a[c] + b[c];
        x[i] = v;
        s += v;
        s2 += v * v;
    }
#pragma unroll
    for (int off = 16; off > 0; off >>= 1) {
        s += __shfl_xor_sync(0xffffffffu, s, off);
        s2 += __shfl_xor_sync(0xffffffffu, s2, off);
    }
    __shared__ float ss[8], ss2[8];
    const int wid = tid >> 5, lane = tid & 31;
    if (lane == 0) { ss[wid] = s; ss2[wid] = s2; }
    __syncthreads();
    float ts = 0.f, ts2 = 0.f;
#pragma unroll
    for (int i = 0; i < 8; i++) { ts += ss[i]; ts2 += ss2[i]; }

    const float mu = ts * (1.f / (float)D_HID);
    const float var = ts2 * (1.f / (float)D_HID) - mu * mu;
    const float rstd = rsqrtf(var + 1e-5f);
#pragma unroll
    for (int i = 0; i < 3; i++) {
        int c = tid + i * 256;
        o[c] = (x[i] - mu) * rstd * g[c] + be[c];
    }
}

// ---------------------------------------------------------------------------
extern "C" void kernel_launch(void* const* d_in, const int* in_sizes, int n_in,
                              void* d_out, int out_size)
{
    const float* X   = (const float*)d_in[0];
    const unsigned int* mask = (const unsigned int*)d_in[1];
    const float* Wq  = (const float*)d_in[2];
    const float* bq  = (const float*)d_in[3];
    const float* Wk  = (const float*)d_in[4];
    const float* bk  = (const float*)d_in[5];
    const float* Wv  = (const float*)d_in[6];
    const float* bv  = (const float*)d_in[7];
    const float* g1  = (const float*)d_in[8];
    const float* be1 = (const float*)d_in[9];
    const float* W1  = (const float*)d_in[10];
    const float* b1  = (const float*)d_in[11];
    const float* W2  = (const float*)d_in[12];
    const float* b2  = (const float*)d_in[13];
    const float* g2  = (const float*)d_in[14];
    const float* be2 = (const float*)d_in[15];
    float* out = (float*)d_out;

    float *q, *k, *v, *attn, *ln1, *hid, *ffn;
    cudaGetSymbolAddress((void**)&q,    g_q);
    cudaGetSymbolAddress((void**)&k,    g_k);
    cudaGetSymbolAddress((void**)&v,    g_v);
    cudaGetSymbolAddress((void**)&attn, g_attn);
    cudaGetSymbolAddress((void**)&ln1,  g_ln1);
    cudaGetSymbolAddress((void**)&hid,  g_hid);
    cudaGetSymbolAddress((void**)&ffn,  g_ffn);

    cudaFuncSetAttribute(flash_kernel,
                         cudaFuncAttributeMaxDynamicSharedMemorySize,
                         FLASH_SMEM);

    dim3 blk(256);

    // QKV projections (scatter into [B,H,S,Dh])
    sgemm_kernel<1><<<dim3(D_HID / 128, M_ROWS / 128), blk>>>(
        X, Wq, bq, q, M_ROWS, D_HID, D_HID);
    sgemm_kernel<1><<<dim3(D_HID / 128, M_ROWS / 128), blk>>>(
        X, Wk, bk, k, M_ROWS, D_HID, D_HID);
    sgemm_kernel<1><<<dim3(D_HID / 128, M_ROWS / 128), blk>>>(
        X, Wv, bv, v, M_ROWS, D_HID, D_HID);

    // attention
    flash_kernel<<<dim3(S_LEN / 64, NH, B_SZ), blk, FLASH_SMEM>>>(
        q, k, v, mask, attn);

    // add & norm 1
    add_ln_kernel<<<M_ROWS, blk>>>(attn, X, g1, be1, ln1);

    // FFN (no activation per reference)
    sgemm_kernel<0><<<dim3(D_FFN / 128, M_ROWS / 128), blk>>>(
        ln1, W1, b1, hid, M_ROWS, D_FFN, D_HID);
    sgemm_kernel<0><<<dim3(D_HID / 128, M_ROWS / 128), blk>>>(
        hid, W2, b2, ffn, M_ROWS, D_HID, D_FFN);

    // add & norm 2 -> output
    add_ln_kernel<<<M_ROWS, blk>>>(ffn, ln1, g2, be2, out);
}

// round 3
// speedup vs baseline: 1.8690x; 1.8690x over previous
#include <cuda_runtime.h>
#include <cuda_bf16.h>
#include <cstdint>
#include <cstddef>

// ---------------------------------------------------------------------------
// EncoderLayer: B=4, S=2048, D=768, H=12, Dh=64, FFN=3072, fp32 in/out
// GEMMs on tensor cores (tf32 mma.sync m16n8k8, fp32 accum).
// Flash attention fp32 (unchanged from R2 - correct baseline).
// ---------------------------------------------------------------------------

#define B_SZ   4
#define S_LEN  2048
#define D_HID  768
#define NH     12
#define DH     64
#define D_FFN  3072
#define M_ROWS (B_SZ * S_LEN)   // 8192

// ---------------- scratch ---------------------------------------------------
__device__ float g_q[M_ROWS * D_HID];
__device__ float g_k[M_ROWS * D_HID];
__device__ float g_v[M_ROWS * D_HID];
__device__ float g_attn[M_ROWS * D_HID];
__device__ float g_ln1[M_ROWS * D_HID];
__device__ float g_hid[(size_t)M_ROWS * D_FFN];
__device__ float g_ffn[M_ROWS * D_HID];

// ---------------------------------------------------------------------------
// tf32 helpers
// ---------------------------------------------------------------------------
__device__ __forceinline__ uint32_t f2tf32(float x) {
    uint32_t r;
    asm("cvt.rna.tf32.f32 %0, %1;" : "=r"(r) : "f"(x));
    return r;
}

__device__ __forceinline__ void mma_tf32(float* c, const uint32_t* a,
                                         const uint32_t* b) {
    asm volatile(
        "mma.sync.aligned.m16n8k8.row.col.f32.tf32.tf32.f32 "
        "{%0,%1,%2,%3}, {%4,%5,%6,%7}, {%8,%9}, {%0,%1,%2,%3};"
        : "+f"(c[0]), "+f"(c[1]), "+f"(c[2]), "+f"(c[3])
        : "r"(a[0]), "r"(a[1]), "r"(a[2]), "r"(a[3]),
          "r"(b[0]), "r"(b[1]));
}

// ---------------------------------------------------------------------------
// GEMM: C[M,N] = A[M,K] @ W[K,N] + bias,   tf32 tensor cores
// Block tile 128x128x32, 256 threads (8 warps as 2x4), warp tile 64x32.
// EPI==0: row-major out ; EPI==1: scatter to [B,H,S,Dh] (QKV)
// ---------------------------------------------------------------------------
#define BM 128
#define BN 128
#define BK 32

template <int EPI>
__global__ void __launch_bounds__(256) gemm_tf32_kernel(
    const float* __restrict__ A, const float* __restrict__ W,
    const float* __restrict__ bias, float* __restrict__ C,
    int M, int N, int K)
{
    __shared__ __align__(16) uint32_t As[BM][36];   // [m][k], pad->stride 36
    __shared__ __align__(16) uint32_t Bs[BK][136];  // [k][n], pad->stride 136

    const int tid  = threadIdx.x;
    const int lane = tid & 31;
    const int warp = tid >> 5;
    const int wm   = warp >> 2;   // 0..1
    const int wn   = warp & 3;    // 0..3
    const int bm   = blockIdx.y * BM;
    const int bn   = blockIdx.x * BN;

    float acc[4][4][4];
#pragma unroll
    for (int mi = 0; mi < 4; mi++)
#pragma unroll
        for (int ni = 0; ni < 4; ni++)
#pragma unroll
            for (int r = 0; r < 4; r++) acc[mi][ni][r] = 0.f;

    float4 ra[4], rb[4];

    // prologue: global load tile k0=0
#pragma unroll
    for (int i = 0; i < 4; i++) {
        int idx = i * 256 + tid;
        int r = idx >> 3, c = (idx & 7) * 4;          // A: 128 rows x 8 f4
        ra[i] = *(const float4*)&A[(size_t)(bm + r) * K + c];
        int kr = idx >> 5, nc = (idx & 31) * 4;       // B: 32 k x 32 f4
        rb[i] = *(const float4*)&W[(size_t)kr * N + bn + nc];
    }
    // convert + store stage
#pragma unroll
    for (int i = 0; i < 4; i++) {
        int idx = i * 256 + tid;
        int r = idx >> 3, c = (idx & 7) * 4;
        uint4 pa = { f2tf32(ra[i].x), f2tf32(ra[i].y),
                     f2tf32(ra[i].z), f2tf32(ra[i].w) };
        *(uint4*)&As[r][c] = pa;
        int kr = idx >> 5, nc = (idx & 31) * 4;
        uint4 pb = { f2tf32(rb[i].x), f2tf32(rb[i].y),
                     f2tf32(rb[i].z), f2tf32(rb[i].w) };
        *(uint4*)&Bs[kr][nc] = pb;
    }

    const int arow  = wm * 64 + (lane >> 2);
    const int bcol0 = wn * 32 + (lane >> 2);
    const int kq    = lane & 3;

    for (int k0 = 0; k0 < K; k0 += BK) {
        __syncthreads();
        const bool has_next = (k0 + BK) < K;
        if (has_next) {
#pragma unroll
            for (int i = 0; i < 4; i++) {
                int idx = i * 256 + tid;
                int r = idx >> 3, c = (idx & 7) * 4;
                ra[i] = *(const float4*)&A[(size_t)(bm + r) * K + k0 + BK + c];
                int kr = idx >> 5, nc = (idx & 31) * 4;
                rb[i] = *(const float4*)&W[(size_t)(k0 + BK + kr) * N + bn + nc];
            }
        }

#pragma unroll
        for (int kk = 0; kk < 4; kk++) {
            const int kr = kk * 8 + kq;
            uint32_t af[4][4], bf[4][2];
#pragma unroll
            for (int mi = 0; mi < 4; mi++) {
                af[mi][0] = As[arow + mi * 16][kr];
                af[mi][1] = As[arow + mi * 16 + 8][kr];
                af[mi][2] = As[arow + mi * 16][kr + 4];
                af[mi][3] = As[arow + mi * 16 + 8][kr + 4];
            }
#pragma unroll
            for (int ni = 0; ni < 4; ni++) {
                bf[ni][0] = Bs[kr][bcol0 + ni * 8];
                bf[ni][1] = Bs[kr + 4][bcol0 + ni * 8];
            }
#pragma unroll
            for (int mi = 0; mi < 4; mi++)
#pragma unroll
                for (int ni = 0; ni < 4; ni++)
                    mma_tf32(acc[mi][ni], af[mi], bf[ni]);
        }
        __syncthreads();
        if (has_next) {
#pragma unroll
            for (int i = 0; i < 4; i++) {
                int idx = i * 256 + tid;
                int r = idx >> 3, c = (idx & 7) * 4;
                uint4 pa = { f2tf32(ra[i].x), f2tf32(ra[i].y),
                             f2tf32(ra[i].z), f2tf32(ra[i].w) };
                *(uint4*)&As[r][c] = pa;
                int kr = idx >> 5, nc = (idx & 31) * 4;
                uint4 pb = { f2tf32(rb[i].x), f2tf32(rb[i].y),
                             f2tf32(rb[i].z), f2tf32(rb[i].w) };
                *(uint4*)&Bs[kr][nc] = pb;
            }
        }
    }

    // epilogue
    const int row_base = bm + wm * 64 + (lane >> 2);
    const int col_base = bn + wn * 32 + (lane & 3) * 2;
#pragma unroll
    for (int ni = 0; ni < 4; ni++) {
        const int c = col_base + ni * 8;
        const float b0 = bias[c], b1 = bias[c + 1];
#pragma unroll
        for (int mi = 0; mi < 4; mi++) {
            const int r0 = row_base + mi * 16;
            const int r1 = r0 + 8;
            float2 v0 = { acc[mi][ni][0] + b0, acc[mi][ni][1] + b1 };
            float2 v1 = { acc[mi][ni][2] + b0, acc[mi][ni][3] + b1 };
            if (EPI == 0) {
                *(float2*)&C[(size_t)r0 * N + c] = v0;
                *(float2*)&C[(size_t)r1 * N + c] = v1;
            } else {
                // m=b*S+s ; n=h*64+dh -> [((b*H+h)*S+s)*64+dh]; dh even
                int h = c >> 6, dh = c & 63;
                {
                    int b_ = r0 >> 11, s_ = r0 & 2047;
                    *(float2*)&C[((size_t)(b_ * NH + h) * S_LEN + s_) * DH + dh] = v0;
                }
                {
                    int b_ = r1 >> 11, s_ = r1 & 2047;
                    *(float2*)&C[((size_t)(b_ * NH + h) * S_LEN + s_) * DH + dh] = v1;
                }
            }
        }
    }
}

// ---------------------------------------------------------------------------
// Flash attention, fp32 (correct baseline from R2).
// ---------------------------------------------------------------------------
#define FLASH_SMEM (4 * 64 * 65 * 4)

__global__ void __launch_bounds__(256) flash_kernel(
    const float* __restrict__ Q, const float* __restrict__ K,
    const float* __restrict__ V, const unsigned int* __restrict__ mask,
    float* __restrict__ out)
{
    extern __shared__ float sm[];
    float (*Qs)[65] = (float(*)[65])(sm);
    float (*Ks)[65] = (float(*)[65])(sm + 64 * 65);
    float (*Vs)[65] = (float(*)[65])(sm + 2 * 64 * 65);
    float (*Ps)[65] = (float(*)[65])(sm + 3 * 64 * 65);

    const int q0 = blockIdx.x * 64;
    const int h = blockIdx.y;
    const int b = blockIdx.z;
    const int tid = threadIdx.x;
    const int tq = tid >> 4;
    const int tk = tid & 15;

    const float* Qg = Q + ((size_t)(b * NH + h) * S_LEN + q0) * DH;
    const float* Kg = K + (size_t)(b * NH + h) * S_LEN * DH;
    const float* Vg = V + (size_t)(b * NH + h) * S_LEN * DH;
    const unsigned int* Mg = mask + ((size_t)b * S_LEN + q0) * S_LEN;

#pragma unroll
    for (int i = 0; i < 16; i++) {
        int idx = i * 256 + tid;
        int r = idx >> 6, d = idx & 63;
        Qs[r][d] = Qg[idx] * 0.125f;
    }

    float m_i[4], l_i[4], o[4][4];
#pragma unroll
    for (int i = 0; i < 4; i++) {
        m_i[i] = -1e30f;
        l_i[i] = 0.f;
#pragma unroll
        for (int j = 0; j < 4; j++) o[i][j] = 0.f;
    }

    for (int kt = 0; kt < S_LEN / 64; kt++) {
        __syncthreads();
#pragma unroll
        for (int i = 0; i < 16; i++) {
            int idx = i * 256 + tid;
            int r = idx >> 6, d = idx & 63;
            Ks[r][d] = Kg[(size_t)kt * 4096 + idx];
            Vs[r][d] = Vg[(size_t)kt * 4096 + idx];
        }
        __syncthreads();

        float s[4][4];
#pragma unroll
        for (int i = 0; i < 4; i++)
#pragma unroll
            for (int j = 0; j < 4; j++) s[i][j] = 0.f;

#pragma unroll 8
        for (int d = 0; d < 64; d++) {
            float qr[4], kr[4];
#pragma unroll
            for (int i = 0; i < 4; i++) qr[i] = Qs[tq * 4 + i][d];
#pragma unroll
            for (int j = 0; j < 4; j++) kr[j] = Ks[tk * 4 + j][d];
#pragma unroll
            for (int i = 0; i < 4; i++)
#pragma unroll
                for (int j = 0; j < 4; j++) s[i][j] += qr[i] * kr[j];
        }

#pragma unroll
        for (int i = 0; i < 4; i++) {
            uint4 mm = *(const uint4*)(Mg + (size_t)(tq * 4 + i) * S_LEN +
                                       kt * 64 + tk * 4);
            if (mm.x) s[i][0] = -1e9f;
            if (mm.y) s[i][1] = -1e9f;
            if (mm.z) s[i][2] = -1e9f;
            if (mm.w) s[i][3] = -1e9f;
        }

#pragma unroll
        for (int i = 0; i < 4; i++) {
            float mt = fmaxf(fmaxf(s[i][0], s[i][1]), fmaxf(s[i][2], s[i][3]));
#pragma unroll
            for (int off = 8; off > 0; off >>= 1)
                mt = fmaxf(mt, __shfl_xor_sync(0xffffffffu, mt, off));
            float mn = fmaxf(m_i[i], mt);
            float alpha = __expf(m_i[i] - mn);
            float ls = 0.f;
#pragma unroll
            for (int j = 0; j < 4; j++) {
                float p = __expf(s[i][j] - mn);
                s[i][j] = p;
                ls += p;
            }
#pragma unroll
            for (int off = 8; off > 0; off >>= 1)
                ls += __shfl_xor_sync(0xffffffffu, ls, off);
            l_i[i] = l_i[i] * alpha + ls;
            m_i[i] = mn;
#pragma unroll
            for (int j = 0; j < 4; j++) o[i][j] *= alpha;
            Ps[tq * 4 + i][tk * 4 + 0] = s[i][0];
            Ps[tq * 4 + i][tk * 4 + 1] = s[i][1];
            Ps[tq * 4 + i][tk * 4 + 2] = s[i][2];
            Ps[tq * 4 + i][tk * 4 + 3] = s[i][3];
        }
        __syncthreads();

#pragma unroll 8
        for (int j = 0; j < 64; j++) {
            float vr[4], pr[4];
#pragma unroll
            for (int jj = 0; jj < 4; jj++) vr[jj] = Vs[j][tk * 4 + jj];
#pragma unroll
            for (int i = 0; i < 4; i++) pr[i] = Ps[tq * 4 + i][j];
#pragma unroll
            for (int i = 0; i < 4; i++)
#pragma unroll
                for (int jj = 0; jj < 4; jj++) o[i][jj] += pr[i] * vr[jj];
        }
    }

#pragma unroll
    for (int i = 0; i < 4; i++) {
        float inv = 1.f / l_i[i];
        size_t base = ((size_t)(b * S_LEN + q0 + tq * 4 + i)) * D_HID + h * DH + tk * 4;
#pragma unroll
        for (int j = 0; j < 4; j++)
            out[base + j] = o[i][j] * inv;
    }
}

// ---------------------------------------------------------------------------
// out = LayerNorm(A + B) * g + beta
// ---------------------------------------------------------------------------
__global__ void __launch_bounds__(256) add_ln_kernel(
    const float* __restrict__ A, const float* __restrict__ Bv,
    const float* __restrict__ g, const float* __restrict__ be,
    float* __restrict__ out)
{
    const int row = blockIdx.x;
    const float* a = A + (size_t)row * D_HID;
    const float* b = Bv + (size_t)row * D_HID;
    float* o = out + (size_t)row * D_HID;
    const int tid = threadIdx.x;

    float x[3];
    float s = 0.f, s2 = 0.f;
#pragma unroll
    for (int i = 0; i < 3; i++) {
        int c = tid + i * 256;
        float v = a[c] + b[c];
        x[i] = v;
        s += v;
        s2 += v * v;
    }
#pragma unroll
    for (int off = 16; off > 0; off >>= 1) {
        s += __shfl_xor_sync(0xffffffffu, s, off);
        s2 += __shfl_xor_sync(0xffffffffu, s2, off);
    }
    __shared__ float ss[8], ss2[8];
    const int wid = tid >> 5, lane = tid & 31;
    if (lane == 0) { ss[wid] = s; ss2[wid] = s2; }
    __syncthreads();
    float ts = 0.f, ts2 = 0.f;
#pragma unroll
    for (int i = 0; i < 8; i++) { ts += ss[i]; ts2 += ss2[i]; }

    const float mu = ts * (1.f / (float)D_HID);
    const float var = ts2 * (1.f / (float)D_HID) - mu * mu;
    const float rstd = rsqrtf(var + 1e-5f);
#pragma unroll
    for (int i = 0; i < 3; i++) {
        int c = tid + i * 256;
        o[c] = (x[i] - mu) * rstd * g[c] + be[c];
    }
}

// ---------------------------------------------------------------------------
extern "C" void kernel_launch(void* const* d_in, const int* in_sizes, int n_in,
                              void* d_out, int out_size)
{
    const float* X   = (const float*)d_in[0];
    const unsigned int* mask = (const unsigned int*)d_in[1];
    const float* Wq  = (const float*)d_in[2];
    const float* bq  = (const float*)d_in[3];
    const float* Wk  = (const float*)d_in[4];
    const float* bk  = (const float*)d_in[5];
    const float* Wv  = (const float*)d_in[6];
    const float* bv  = (const float*)d_in[7];
    const float* g1  = (const float*)d_in[8];
    const float* be1 = (const float*)d_in[9];
    const float* W1  = (const float*)d_in[10];
    const float* b1  = (const float*)d_in[11];
    const float* W2  = (const float*)d_in[12];
    const float* b2  = (const float*)d_in[13];
    const float* g2  = (const float*)d_in[14];
    const float* be2 = (const float*)d_in[15];
    float* out = (float*)d_out;

    float *q, *k, *v, *attn, *ln1, *hid, *ffn;
    cudaGetSymbolAddress((void**)&q,    g_q);
    cudaGetSymbolAddress((void**)&k,    g_k);
    cudaGetSymbolAddress((void**)&v,    g_v);
    cudaGetSymbolAddress((void**)&attn, g_attn);
    cudaGetSymbolAddress((void**)&ln1,  g_ln1);
    cudaGetSymbolAddress((void**)&hid,  g_hid);
    cudaGetSymbolAddress((void**)&ffn,  g_ffn);

    cudaFuncSetAttribute(flash_kernel,
                         cudaFuncAttributeMaxDynamicSharedMemorySize,
                         FLASH_SMEM);

    dim3 blk(256);

    // QKV projections (tensor cores, scatter into [B,H,S,Dh])
    gemm_tf32_kernel<1><<<dim3(D_HID / 128, M_ROWS / 128), blk>>>(
        X, Wq, bq, q, M_ROWS, D_HID, D_HID);
    gemm_tf32_kernel<1><<<dim3(D_HID / 128, M_ROWS / 128), blk>>>(
        X, Wk, bk, k, M_ROWS, D_HID, D_HID);
    gemm_tf32_kernel<1><<<dim3(D_HID / 128, M_ROWS / 128), blk>>>(
        X, Wv, bv, v, M_ROWS, D_HID, D_HID);

    // attention
    flash_kernel<<<dim3(S_LEN / 64, NH, B_SZ), blk, FLASH_SMEM>>>(
        q, k, v, mask, attn);

    // add & norm 1
    add_ln_kernel<<<M_ROWS, blk>>>(attn, X, g1, be1, ln1);

    // FFN
    gemm_tf32_kernel<0><<<dim3(D_FFN / 128, M_ROWS / 128), blk>>>(
        ln1, W1, b1, hid, M_ROWS, D_FFN, D_HID);
    gemm_tf32_kernel<0><<<dim3(D_HID / 128, M_ROWS / 128), blk>>>(
        hid, W2, b2, ffn, M_ROWS, D_HID, D_FFN);

    // add & norm 2 -> output
    add_ln_kernel<<<M_ROWS, blk>>>(ffn, ln1, g2, be2, out);
}

// round 4
// speedup vs baseline: 2.9092x; 1.5565x over previous
#include <cuda_runtime.h>
#include <cuda_bf16.h>
#include <cstdint>
#include <cstddef>

// ---------------------------------------------------------------------------
// EncoderLayer: B=4, S=2048, D=768, H=12, Dh=64, FFN=3072, fp32 in/out
// GEMMs + flash attention on tensor cores (tf32 mma.sync m16n8k8, fp32 accum)
// ---------------------------------------------------------------------------

#define B_SZ   4
#define S_LEN  2048
#define D_HID  768
#define NH     12
#define DH     64
#define D_FFN  3072
#define M_ROWS (B_SZ * S_LEN)   // 8192

// ---------------- scratch ---------------------------------------------------
__device__ float g_q[M_ROWS * D_HID];
__device__ float g_k[M_ROWS * D_HID];
__device__ float g_v[M_ROWS * D_HID];
__device__ float g_attn[M_ROWS * D_HID];
__device__ float g_ln1[M_ROWS * D_HID];
__device__ float g_hid[(size_t)M_ROWS * D_FFN];
__device__ float g_ffn[M_ROWS * D_HID];

// ---------------------------------------------------------------------------
__device__ __forceinline__ uint32_t f2tf32(float x) {
    uint32_t r;
    asm("cvt.rna.tf32.f32 %0, %1;" : "=r"(r) : "f"(x));
    return r;
}

__device__ __forceinline__ void mma_tf32(float* c, const uint32_t* a,
                                         const uint32_t* b) {
    asm volatile(
        "mma.sync.aligned.m16n8k8.row.col.f32.tf32.tf32.f32 "
        "{%0,%1,%2,%3}, {%4,%5,%6,%7}, {%8,%9}, {%0,%1,%2,%3};"
        : "+f"(c[0]), "+f"(c[1]), "+f"(c[2]), "+f"(c[3])
        : "r"(a[0]), "r"(a[1]), "r"(a[2]), "r"(a[3]),
          "r"(b[0]), "r"(b[1]));
}

// ---------------------------------------------------------------------------
// GEMM: C[M,N] = A[M,K] @ W[K,N] + bias,   tf32 tensor cores (from R3)
// ---------------------------------------------------------------------------
#define BM 128
#define BN 128
#define BK 32

template <int EPI>
__global__ void __launch_bounds__(256) gemm_tf32_kernel(
    const float* __restrict__ A, const float* __restrict__ W,
    const float* __restrict__ bias, float* __restrict__ C,
    int M, int N, int K)
{
    __shared__ __align__(16) uint32_t As[BM][36];
    __shared__ __align__(16) uint32_t Bs[BK][136];

    const int tid  = threadIdx.x;
    const int lane = tid & 31;
    const int warp = tid >> 5;
    const int wm   = warp >> 2;
    const int wn   = warp & 3;
    const int bm   = blockIdx.y * BM;
    const int bn   = blockIdx.x * BN;

    float acc[4][4][4];
#pragma unroll
    for (int mi = 0; mi < 4; mi++)
#pragma unroll
        for (int ni = 0; ni < 4; ni++)
#pragma unroll
            for (int r = 0; r < 4; r++) acc[mi][ni][r] = 0.f;

    float4 ra[4], rb[4];

#pragma unroll
    for (int i = 0; i < 4; i++) {
        int idx = i * 256 + tid;
        int r = idx >> 3, c = (idx & 7) * 4;
        ra[i] = *(const float4*)&A[(size_t)(bm + r) * K + c];
        int kr = idx >> 5, nc = (idx & 31) * 4;
        rb[i] = *(const float4*)&W[(size_t)kr * N + bn + nc];
    }
#pragma unroll
    for (int i = 0; i < 4; i++) {
        int idx = i * 256 + tid;
        int r = idx >> 3, c = (idx & 7) * 4;
        uint4 pa = { f2tf32(ra[i].x), f2tf32(ra[i].y),
                     f2tf32(ra[i].z), f2tf32(ra[i].w) };
        *(uint4*)&As[r][c] = pa;
        int kr = idx >> 5, nc = (idx & 31) * 4;
        uint4 pb = { f2tf32(rb[i].x), f2tf32(rb[i].y),
                     f2tf32(rb[i].z), f2tf32(rb[i].w) };
        *(uint4*)&Bs[kr][nc] = pb;
    }

    const int arow  = wm * 64 + (lane >> 2);
    const int bcol0 = wn * 32 + (lane >> 2);
    const int kq    = lane & 3;

    for (int k0 = 0; k0 < K; k0 += BK) {
        __syncthreads();
        const bool has_next = (k0 + BK) < K;
        if (has_next) {
#pragma unroll
            for (int i = 0; i < 4; i++) {
                int idx = i * 256 + tid;
                int r = idx >> 3, c = (idx & 7) * 4;
                ra[i] = *(const float4*)&A[(size_t)(bm + r) * K + k0 + BK + c];
                int kr = idx >> 5, nc = (idx & 31) * 4;
                rb[i] = *(const float4*)&W[(size_t)(k0 + BK + kr) * N + bn + nc];
            }
        }

#pragma unroll
        for (int kk = 0; kk < 4; kk++) {
            const int kr = kk * 8 + kq;
            uint32_t af[4][4], bf[4][2];
#pragma unroll
            for (int mi = 0; mi < 4; mi++) {
                af[mi][0] = As[arow + mi * 16][kr];
                af[mi][1] = As[arow + mi * 16 + 8][kr];
                af[mi][2] = As[arow + mi * 16][kr + 4];
                af[mi][3] = As[arow + mi * 16 + 8][kr + 4];
            }
#pragma unroll
            for (int ni = 0; ni < 4; ni++) {
                bf[ni][0] = Bs[kr][bcol0 + ni * 8];
                bf[ni][1] = Bs[kr + 4][bcol0 + ni * 8];
            }
#pragma unroll
            for (int mi = 0; mi < 4; mi++)
#pragma unroll
                for (int ni = 0; ni < 4; ni++)
                    mma_tf32(acc[mi][ni], af[mi], bf[ni]);
        }
        __syncthreads();
        if (has_next) {
#pragma unroll
            for (int i = 0; i < 4; i++) {
                int idx = i * 256 + tid;
                int r = idx >> 3, c = (idx & 7) * 4;
                uint4 pa = { f2tf32(ra[i].x), f2tf32(ra[i].y),
                             f2tf32(ra[i].z), f2tf32(ra[i].w) };
                *(uint4*)&As[r][c] = pa;
                int kr = idx >> 5, nc = (idx & 31) * 4;
                uint4 pb = { f2tf32(rb[i].x), f2tf32(rb[i].y),
                             f2tf32(rb[i].z), f2tf32(rb[i].w) };
                *(uint4*)&Bs[kr][nc] = pb;
            }
        }
    }

    const int row_base = bm + wm * 64 + (lane >> 2);
    const int col_base = bn + wn * 32 + (lane & 3) * 2;
#pragma unroll
    for (int ni = 0; ni < 4; ni++) {
        const int c = col_base + ni * 8;
        const float b0 = bias[c], b1 = bias[c + 1];
#pragma unroll
        for (int mi = 0; mi < 4; mi++) {
            const int r0 = row_base + mi * 16;
            const int r1 = r0 + 8;
            float2 v0 = { acc[mi][ni][0] + b0, acc[mi][ni][1] + b1 };
            float2 v1 = { acc[mi][ni][2] + b0, acc[mi][ni][3] + b1 };
            if (EPI == 0) {
                *(float2*)&C[(size_t)r0 * N + c] = v0;
                *(float2*)&C[(size_t)r1 * N + c] = v1;
            } else {
                int h = c >> 6, dh = c & 63;
                {
                    int b_ = r0 >> 11, s_ = r0 & 2047;
                    *(float2*)&C[((size_t)(b_ * NH + h) * S_LEN + s_) * DH + dh] = v0;
                }
                {
                    int b_ = r1 >> 11, s_ = r1 & 2047;
                    *(float2*)&C[((size_t)(b_ * NH + h) * S_LEN + s_) * DH + dh] = v1;
                }
            }
        }
    }
}

// ---------------------------------------------------------------------------
// Flash attention on tf32 tensor cores.
// Block: 128 queries x one (b,h). 8 warps; warp owns 16 query rows.
// Key tiles of 64. QK^T and PV via m16n8k8; softmax on accumulator layout.
// Smem strides: Q/P 68 (a-frag conflict-free), K 68 (b-frag cf), V 72 (b-frag cf).
// ---------------------------------------------------------------------------
#define SQP 68
#define SKK 68
#define SVV 72
// words: QP 128*68=8704, Ks 64*68=4352, Vs 64*72=4608  -> 17664 w = 70656 B
#define FLASH_SMEM (17664 * 4)

__global__ void __launch_bounds__(256) flash_tf32_kernel(
    const float* __restrict__ Q, const float* __restrict__ K,
    const float* __restrict__ V, const unsigned int* __restrict__ mask,
    float* __restrict__ out)
{
    extern __shared__ uint32_t sm[];
    uint32_t* QP = sm;                 // Q tile, later reused as P per-warp
    uint32_t* Ks = sm + 128 * SQP;
    uint32_t* Vs = Ks + 64 * SKK;

    const int q0   = blockIdx.x * 128;
    const int h    = blockIdx.y;
    const int b    = blockIdx.z;
    const int tid  = threadIdx.x;
    const int lane = tid & 31;
    const int warp = tid >> 5;
    const int lr   = lane >> 2;        // 0..7 row within fragment
    const int lc   = lane & 3;         // 0..3 col group

    const float* Qg = Q + ((size_t)(b * NH + h) * S_LEN + q0) * DH;
    const float* Kg = K + (size_t)(b * NH + h) * S_LEN * DH;
    const float* Vg = V + (size_t)(b * NH + h) * S_LEN * DH;
    const unsigned int* Mg = mask + ((size_t)b * S_LEN + q0) * S_LEN;

    // ---- load Q tile (scaled 1/8, tf32) ----
#pragma unroll
    for (int i = 0; i < 8; i++) {
        int idx = i * 256 + tid;       // 2048 float4 total
        int r = idx >> 4, c = (idx & 15) * 4;
        float4 qv = *(const float4*)&Qg[(size_t)r * DH + c];
        QP[r * SQP + c]     = f2tf32(qv.x * 0.125f);
        QP[r * SQP + c + 1] = f2tf32(qv.y * 0.125f);
        QP[r * SQP + c + 2] = f2tf32(qv.z * 0.125f);
        QP[r * SQP + c + 3] = f2tf32(qv.w * 0.125f);
    }
    __syncthreads();

    // ---- Q fragments (register resident) ----
    const int qrow = warp * 16 + lr;
    uint32_t qa[8][4];
#pragma unroll
    for (int kk = 0; kk < 8; kk++) {
        int cb = kk * 8 + lc;
        qa[kk][0] = QP[qrow * SQP + cb];
        qa[kk][1] = QP[(qrow + 8) * SQP + cb];
        qa[kk][2] = QP[qrow * SQP + cb + 4];
        qa[kk][3] = QP[(qrow + 8) * SQP + cb + 4];
    }

    float m0 = -1e30f, m1 = -1e30f, l0 = 0.f, l1 = 0.f;
    float o[8][4];
#pragma unroll
    for (int nt = 0; nt < 8; nt++)
#pragma unroll
        for (int r = 0; r < 4; r++) o[nt][r] = 0.f;

    uint32_t* Pw = QP + warp * 16 * SQP;   // per-warp P region

    for (int kt = 0; kt < S_LEN / 64; kt++) {
        __syncthreads();
        // load K,V tiles (64x64 each), tf32
#pragma unroll
        for (int i = 0; i < 4; i++) {
            int idx = i * 256 + tid;   // 1024 float4 per matrix
            int r = idx >> 4, c = (idx & 15) * 4;
            float4 kv = *(const float4*)&Kg[(size_t)kt * 4096 + r * DH + c];
            Ks[r * SKK + c]     = f2tf32(kv.x);
            Ks[r * SKK + c + 1] = f2tf32(kv.y);
            Ks[r * SKK + c + 2] = f2tf32(kv.z);
            Ks[r * SKK + c + 3] = f2tf32(kv.w);
            float4 vv = *(const float4*)&Vg[(size_t)kt * 4096 + r * DH + c];
            Vs[r * SVV + c]     = f2tf32(vv.x);
            Vs[r * SVV + c + 1] = f2tf32(vv.y);
            Vs[r * SVV + c + 2] = f2tf32(vv.z);
            Vs[r * SVV + c + 3] = f2tf32(vv.w);
        }
        __syncthreads();

        // ---- S = Q K^T ----
        float s[8][4];
#pragma unroll
        for (int nt = 0; nt < 8; nt++)
#pragma unroll
            for (int r = 0; r < 4; r++) s[nt][r] = 0.f;

#pragma unroll
        for (int kk = 0; kk < 8; kk++) {
#pragma unroll
            for (int nt = 0; nt < 8; nt++) {
                uint32_t bf[2];
                bf[0] = Ks[(nt * 8 + lr) * SKK + kk * 8 + lc];
                bf[1] = Ks[(nt * 8 + lr) * SKK + kk * 8 + lc + 4];
                mma_tf32(s[nt], qa[kk], bf);
            }
        }

        // ---- mask ----
#pragma unroll
        for (int nt = 0; nt < 8; nt++) {
            const size_t mcol = (size_t)kt * 64 + nt * 8 + 2 * lc;
            uint2 mm0 = *(const uint2*)&Mg[(size_t)(warp * 16 + lr) * S_LEN + mcol];
            uint2 mm1 = *(const uint2*)&Mg[(size_t)(warp * 16 + lr + 8) * S_LEN + mcol];
            if (mm0.x) s[nt][0] = -1e9f;
            if (mm0.y) s[nt][1] = -1e9f;
            if (mm1.x) s[nt][2] = -1e9f;
            if (mm1.y) s[nt][3] = -1e9f;
        }

        // ---- online softmax (rows qrow, qrow+8) ----
        float mt0 = -1e30f, mt1 = -1e30f;
#pragma unroll
        for (int nt = 0; nt < 8; nt++) {
            mt0 = fmaxf(mt0, fmaxf(s[nt][0], s[nt][1]));
            mt1 = fmaxf(mt1, fmaxf(s[nt][2], s[nt][3]));
        }
        mt0 = fmaxf(mt0, __shfl_xor_sync(0xffffffffu, mt0, 1));
        mt0 = fmaxf(mt0, __shfl_xor_sync(0xffffffffu, mt0, 2));
        mt1 = fmaxf(mt1, __shfl_xor_sync(0xffffffffu, mt1, 1));
        mt1 = fmaxf(mt1, __shfl_xor_sync(0xffffffffu, mt1, 2));

        float mn0 = fmaxf(m0, mt0), mn1 = fmaxf(m1, mt1);
        float a0 = __expf(m0 - mn0), a1 = __expf(m1 - mn1);
        float ls0 = 0.f, ls1 = 0.f;
#pragma unroll
        for (int nt = 0; nt < 8; nt++) {
            s[nt][0] = __expf(s[nt][0] - mn0);
            s[nt][1] = __expf(s[nt][1] - mn0);
            s[nt][2] = __expf(s[nt][2] - mn1);
            s[nt][3] = __expf(s[nt][3] - mn1);
            ls0 += s[nt][0] + s[nt][1];
            ls1 += s[nt][2] + s[nt][3];
        }
        ls0 += __shfl_xor_sync(0xffffffffu, ls0, 1);
        ls0 += __shfl_xor_sync(0xffffffffu, ls0, 2);
        ls1 += __shfl_xor_sync(0xffffffffu, ls1, 1);
        ls1 += __shfl_xor_sync(0xffffffffu, ls1, 2);
        l0 = l0 * a0 + ls0;
        l1 = l1 * a1 + ls1;
        m0 = mn0; m1 = mn1;
#pragma unroll
        for (int nt = 0; nt < 8; nt++) {
            o[nt][0] *= a0; o[nt][1] *= a0;
            o[nt][2] *= a1; o[nt][3] *= a1;
        }

        // ---- P -> smem (tf32) ----
#pragma unroll
        for (int nt = 0; nt < 8; nt++) {
            Pw[lr * SQP + nt * 8 + 2 * lc]           = f2tf32(s[nt][0]);
            Pw[lr * SQP + nt * 8 + 2 * lc + 1]       = f2tf32(s[nt][1]);
            Pw[(lr + 8) * SQP + nt * 8 + 2 * lc]     = f2tf32(s[nt][2]);
            Pw[(lr + 8) * SQP + nt * 8 + 2 * lc + 1] = f2tf32(s[nt][3]);
        }
        __syncwarp();

        // ---- O += P V ----
#pragma unroll
        for (int kk = 0; kk < 8; kk++) {
            uint32_t pa[4];
            pa[0] = Pw[lr * SQP + kk * 8 + lc];
            pa[1] = Pw[(lr + 8) * SQP + kk * 8 + lc];
            pa[2] = Pw[lr * SQP + kk * 8 + lc + 4];
            pa[3] = Pw[(lr + 8) * SQP + kk * 8 + lc + 4];
#pragma unroll
            for (int nt = 0; nt < 8; nt++) {
                uint32_t bf[2];
                bf[0] = Vs[(kk * 8 + lc) * SVV + nt * 8 + lr];
                bf[1] = Vs[(kk * 8 + lc + 4) * SVV + nt * 8 + lr];
                mma_tf32(o[nt], pa, bf);
            }
        }
        // loop-top __syncthreads() orders P reads vs next-iteration writes
    }

    // ---- write out [B,S,D] ----
    const float inv0 = 1.f / l0, inv1 = 1.f / l1;
    const size_t base0 = ((size_t)(b * S_LEN + q0 + warp * 16 + lr)) * D_HID + h * DH;
    const size_t base1 = base0 + 8 * D_HID;
#pragma unroll
    for (int nt = 0; nt < 8; nt++) {
        const int c = nt * 8 + 2 * lc;
        float2 v0 = { o[nt][0] * inv0, o[nt][1] * inv0 };
        float2 v1 = { o[nt][2] * inv1, o[nt][3] * inv1 };
        *(float2*)&out[base0 + c] = v0;
        *(float2*)&out[base1 + c] = v1;
    }
}

// ---------------------------------------------------------------------------
// out = LayerNorm(A + B) * g + beta
// ---------------------------------------------------------------------------
__global__ void __launch_bounds__(256) add_ln_kernel(
    const float* __restrict__ A, const float* __restrict__ Bv,
    const float* __restrict__ g, const float* __restrict__ be,
    float* __restrict__ out)
{
    const int row = blockIdx.x;
    const float* a = A + (size_t)row * D_HID;
    const float* b = Bv + (size_t)row * D_HID;
    float* o = out + (size_t)row * D_HID;
    const int tid = threadIdx.x;

    float x[3];
    float s = 0.f, s2 = 0.f;
#pragma unroll
    for (int i = 0; i < 3; i++) {
        int c = tid + i * 256;
        float v = a[c] + b[c];
        x[i] = v;
        s += v;
        s2 += v * v;
    }
#pragma unroll
    for (int off = 16; off > 0; off >>= 1) {
        s += __shfl_xor_sync(0xffffffffu, s, off);
        s2 += __shfl_xor_sync(0xffffffffu, s2, off);
    }
    __shared__ float ss[8], ss2[8];
    const int wid = tid >> 5, lane = tid & 31;
    if (lane == 0) { ss[wid] = s; ss2[wid] = s2; }
    __syncthreads();
    float ts = 0.f, ts2 = 0.f;
#pragma unroll
    for (int i = 0; i < 8; i++) { ts += ss[i]; ts2 += ss2[i]; }

    const float mu = ts * (1.f / (float)D_HID);
    const float var = ts2 * (1.f / (float)D_HID) - mu * mu;
    const float rstd = rsqrtf(var + 1e-5f);
#pragma unroll
    for (int i = 0; i < 3; i++) {
        int c = tid + i * 256;
        o[c] = (x[i] - mu) * rstd * g[c] + be[c];
    }
}

// ---------------------------------------------------------------------------
extern "C" void kernel_launch(void* const* d_in, const int* in_sizes, int n_in,
                              void* d_out, int out_size)
{
    const float* X   = (const float*)d_in[0];
    const unsigned int* mask = (const unsigned int*)d_in[1];
    const float* Wq  = (const float*)d_in[2];
    const float* bq  = (const float*)d_in[3];
    const float* Wk  = (const float*)d_in[4];
    const float* bk  = (const float*)d_in[5];
    const float* Wv  = (const float*)d_in[6];
    const float* bv  = (const float*)d_in[7];
    const float* g1  = (const float*)d_in[8];
    const float* be1 = (const float*)d_in[9];
    const float* W1  = (const float*)d_in[10];
    const float* b1  = (const float*)d_in[11];
    const float* W2  = (const float*)d_in[12];
    const float* b2  = (const float*)d_in[13];
    const float* g2  = (const float*)d_in[14];
    const float* be2 = (const float*)d_in[15];
    float* out = (float*)d_out;

    float *q, *k, *v, *attn, *ln1, *hid, *ffn;
    cudaGetSymbolAddress((void**)&q,    g_q);
    cudaGetSymbolAddress((void**)&k,    g_k);
    cudaGetSymbolAddress((void**)&v,    g_v);
    cudaGetSymbolAddress((void**)&attn, g_attn);
    cudaGetSymbolAddress((void**)&ln1,  g_ln1);
    cudaGetSymbolAddress((void**)&hid,  g_hid);
    cudaGetSymbolAddress((void**)&ffn,  g_ffn);

    cudaFuncSetAttribute(flash_tf32_kernel,
                         cudaFuncAttributeMaxDynamicSharedMemorySize,
                         FLASH_SMEM);

    dim3 blk(256);

    // QKV projections (tensor cores, scatter into [B,H,S,Dh])
    gemm_tf32_kernel<1><<<dim3(D_HID / 128, M_ROWS / 128), blk>>>(
        X, Wq, bq, q, M_ROWS, D_HID, D_HID);
    gemm_tf32_kernel<1><<<dim3(D_HID / 128, M_ROWS / 128), blk>>>(
        X, Wk, bk, k, M_ROWS, D_HID, D_HID);
    gemm_tf32_kernel<1><<<dim3(D_HID / 128, M_ROWS / 128), blk>>>(
        X, Wv, bv, v, M_ROWS, D_HID, D_HID);

    // attention (tensor cores)
    flash_tf32_kernel<<<dim3(S_LEN / 128, NH, B_SZ), blk, FLASH_SMEM>>>(
        q, k, v, mask, attn);

    // add & norm 1
    add_ln_kernel<<<M_ROWS, blk>>>(attn, X, g1, be1, ln1);

    // FFN
    gemm_tf32_kernel<0><<<dim3(D_FFN / 128, M_ROWS / 128), blk>>>(
        ln1, W1, b1, hid, M_ROWS, D_FFN, D_HID);
    gemm_tf32_kernel<0><<<dim3(D_HID / 128, M_ROWS / 128), blk>>>(
        hid, W2, b2, ffn, M_ROWS, D_HID, D_FFN);

    // add & norm 2 -> output
    add_ln_kernel<<<M_ROWS, blk>>>(ffn, ln1, g2, be2, out);
}